// round 2
// baseline (speedup 1.0000x reference)
#include <cuda_runtime.h>
#include <cstdint>

#define Bk 128
#define Sk 128
#define Ek 256
#define Dk 512
#define Kk 16
#define Lk 1906
#define Rk 2033
#define Tk 127
#define TINYF 1.17549435e-38f

__device__ float g_h[2][Bk][Dk];
__device__ float g_x[Bk][Dk];
__device__ float g_last_t[Bk];
__device__ int   g_last_m[Bk];
__device__ int   g_chosen[Bk];
__device__ int   g_cand[Bk][Lk];
__device__ float g_prob[Bk][Lk];
__device__ float g_nrec[Bk][Rk];
__device__ unsigned int g_keys[Tk][2];

// JAX threefry2x32 (exact rotation/key schedule of jax._src.prng lowering)
__device__ __forceinline__ void tf2x32(uint32_t k0, uint32_t k1,
                                       uint32_t x0, uint32_t x1,
                                       uint32_t& o0, uint32_t& o1) {
  uint32_t ks2 = k0 ^ k1 ^ 0x1BD11BDAu;
  x0 += k0; x1 += k1;
#define RR(d) { x0 += x1; x1 = (x1 << d) | (x1 >> (32 - d)); x1 ^= x0; }
  RR(13) RR(15) RR(26) RR(6)  x0 += k1;  x1 += ks2 + 1u;
  RR(17) RR(29) RR(16) RR(24) x0 += ks2; x1 += k0 + 2u;
  RR(13) RR(15) RR(26) RR(6)  x0 += k0;  x1 += k1 + 3u;
  RR(17) RR(29) RR(16) RR(24) x0 += k1;  x1 += ks2 + 4u;
  RR(13) RR(15) RR(26) RR(6)  x0 += ks2; x1 += k0 + 5u;
#undef RR
  o0 = x0; o1 = x1;
}

__global__ void init_kernel(const int* __restrict__ marker,
                            const float* __restrict__ timed,
                            const float* __restrict__ maskd,
                            float* __restrict__ out) {
  int idx = blockIdx.x * blockDim.x + threadIdx.x;
  if (idx < Bk * Rk) g_nrec[idx / Rk][idx % Rk] = 1.0f;
  if (idx < Bk * Lk) {
    int b = idx / Lk, l = idx % Lk;
    g_prob[b][l] = (l == 0) ? 1.0f : 0.0f;
    g_cand[b][l] = (l == 0) ? marker[b * Sk] : 0;
  }
  if (idx < 2 * Bk * Dk) ((float*)g_h)[idx] = 0.0f;
  if (idx < Bk) {
    int b = idx;
    g_last_t[b] = timed[b * Sk];
    g_last_m[b] = marker[b * Sk];
    g_chosen[b] = 0;
    out[0 * 16384 + b * Sk] = (float)marker[b * Sk];
    out[1 * 16384 + b * Sk] = timed[b * Sk];
    out[2 * 16384 + b * Sk] = maskd[b * Sk];
    out[3 * 16384 + b * Sk] = 1.0f;
    out[4 * 16384 + b * Sk] = 1.0f;
  }
  if (idx < Tk) {
    // partitionable/foldlike split: keys[t] = threefry2x32((0,42), (0, t))
    uint32_t o0, o1;
    tf2x32(0u, 42u, 0u, (uint32_t)idx, o0, o1);
    g_keys[idx][0] = o0;
    g_keys[idx][1] = o1;
  }
}

// x = leaky(vec @ W_el + b_el), vec = emb[last_m] + 0.1*(last_t*W_te + b_te)
// grid (16 d-chunks x 8 b-chunks), 256 threads
__global__ void kx_kernel(const float* __restrict__ emb,
                          const float* __restrict__ W_te,
                          const float* __restrict__ b_te,
                          const float* __restrict__ W_el,
                          const float* __restrict__ b_el) {
  __shared__ float vec[16][Ek];
  int dc = blockIdx.x, bc = blockIdx.y;
  int tid = threadIdx.x;
  for (int i = tid; i < 16 * Ek; i += 256) {
    int bl = i >> 8, e = i & 255;
    int b = bc * 16 + bl;
    float te = __fadd_rn(__fmul_rn(g_last_t[b], W_te[e]), b_te[e]);
    vec[bl][e] = __fadd_rn(emb[(long)g_last_m[b] * Ek + e], __fmul_rn(0.1f, te));
  }
  __syncthreads();
  int dl = tid & 31, bg = tid >> 5;
  int d = dc * 32 + dl;
  int b0 = bg * 2, b1 = b0 + 1;
  float a0 = 0.0f, a1 = 0.0f;
  for (int e = 0; e < Ek; e++) {
    float w = W_el[e * Dk + d];
    a0 = fmaf(vec[b0][e], w, a0);
    a1 = fmaf(vec[b1][e], w, a1);
  }
  float bb = b_el[d];
  a0 = __fadd_rn(a0, bb);
  a1 = __fadd_rn(a1, bb);
  g_x[bc * 16 + b0][d] = (a0 >= 0.0f) ? a0 : __fmul_rn(0.01f, a0);
  g_x[bc * 16 + b1][d] = (a1 >= 0.0f) ? a1 : __fmul_rn(0.01f, a1);
}

// h_new = tanh(((x@W_ih + b_ih) + h@W_hh) + b_hh)
// grid (16 d-chunks x 8 b-chunks), 256 threads, e-chunked smem staging
__global__ void kh_kernel(const float* __restrict__ W_ih,
                          const float* __restrict__ b_ih,
                          const float* __restrict__ W_hh,
                          const float* __restrict__ b_hh,
                          int hin, int hout) {
  __shared__ float xs[16][128], hs[16][128];
  int dc = blockIdx.x, bc = blockIdx.y;
  int tid = threadIdx.x;
  int dl = tid & 31, bg = tid >> 5;
  int d = dc * 32 + dl;
  int b0 = bg * 2, b1 = b0 + 1;
  float ax0 = 0, ax1 = 0, ah0 = 0, ah1 = 0;
  for (int ch = 0; ch < 4; ch++) {
    __syncthreads();
    for (int i = tid; i < 16 * 128; i += 256) {
      int bl = i >> 7, e = i & 127;
      xs[bl][e] = g_x[bc * 16 + bl][ch * 128 + e];
      hs[bl][e] = g_h[hin][bc * 16 + bl][ch * 128 + e];
    }
    __syncthreads();
    const float* wi = W_ih + (ch * 128) * Dk + d;
    const float* wh = W_hh + (ch * 128) * Dk + d;
#pragma unroll 8
    for (int e = 0; e < 128; e++) {
      float w1 = wi[e * Dk];
      float w2 = wh[e * Dk];
      ax0 = fmaf(xs[b0][e], w1, ax0);
      ax1 = fmaf(xs[b1][e], w1, ax1);
      ah0 = fmaf(hs[b0][e], w2, ah0);
      ah1 = fmaf(hs[b1][e], w2, ah1);
    }
  }
  float bi = b_ih[d], bh = b_hh[d];
  g_h[hout][bc * 16 + b0][d] = tanhf(__fadd_rn(__fadd_rn(__fadd_rn(ax0, bi), ah0), bh));
  g_h[hout][bc * 16 + b1][d] = tanhf(__fadd_rn(__fadd_rn(__fadd_rn(ax1, bi), ah1), bh));
}

// per-batch-row: dt/softplus, neighbor scores+softmax, prob/cand/nrec updates,
// JAX-exact gumbel sampling + first-index argmax, output writes
__global__ void ks_kernel(const float* __restrict__ emb,
                          const int* __restrict__ nlist,
                          const float* __restrict__ nprob,
                          const float* __restrict__ W_time,
                          const float* __restrict__ b_time,
                          const float* __restrict__ W_mk,
                          const float* __restrict__ b_mk,
                          int h_idx, int t, float* __restrict__ out) {
  int b = blockIdx.x;
  int tid = threadIdx.x;
  const float* h = g_h[h_idx][b];
  __shared__ float s_part[256];
  __shared__ float s_score[Kk];
  __shared__ int s_neigh[Kk];
  __shared__ float s_val[256];
  __shared__ int s_idx[256];

  // dt partials (512-dot)
  {
    float a = __fmul_rn(h[2 * tid], W_time[2 * tid]);
    a = fmaf(h[2 * tid + 1], W_time[2 * tid + 1], a);
    s_part[tid] = a;
  }
  int lm = g_last_m[b];
  if (tid < Kk) {
    s_neigh[tid] = nlist[lm * Kk + tid];
    g_nrec[b][1 + t * Kk + tid] = nprob[lm * Kk + tid];
  }
  __syncthreads();

  float newt = 0.0f;
  if (tid == 0) {
    float s = 0.0f;
    for (int i = 0; i < 256; i++) s = __fadd_rn(s, s_part[i]);
    float xx = __fadd_rn(s, b_time[0]);
    // jnp.logaddexp(x, 0) = max(x,0) + log1p(exp(-|x|))
    float sp = __fadd_rn(fmaxf(xx, 0.0f), log1pf(expf(-fabsf(xx))));
    newt = __fadd_rn(g_last_t[b], sp);
  }

  // 16 neighbor scores: dot([emb[neigh], h], W_mk) + b_mk  (len 768)
  int warp = tid >> 5, lane = tid & 31;
  for (int k = warp; k < Kk; k += 8) {
    const float* ev = emb + (long)s_neigh[k] * Ek;
    float acc = 0.0f;
    for (int i = lane; i < Ek + Dk; i += 32) {
      float v = (i < Ek) ? ev[i] : h[i - Ek];
      acc = fmaf(v, W_mk[i], acc);
    }
    for (int o = 16; o; o >>= 1) acc += __shfl_down_sync(0xffffffffu, acc, o);
    if (lane == 0) s_score[k] = __fadd_rn(acc, b_mk[0]);
  }
  __syncthreads();

  if (tid == 0) {
    float mx = s_score[0];
    for (int k = 1; k < Kk; k++) mx = fmaxf(mx, s_score[k]);
    float ee[Kk]; float ssum = 0.0f;
    for (int k = 0; k < Kk; k++) {
      ee[k] = expf(__fadd_rn(s_score[k], -mx));
      ssum = __fadd_rn(ssum, ee[k]);
    }
    int ch = g_chosen[b];
    float cp = g_prob[b][ch];
    // attached = cp * mprob  (plain fp32 mul; denormal underflow must match)
    g_prob[b][ch] = __fmul_rn(cp, __fdiv_rn(ee[0], ssum));
    int base = 1 + t * (Kk - 1);
    for (int k = 1; k < Kk; k++) {
      g_prob[b][base + k - 1] = __fmul_rn(cp, __fdiv_rn(ee[k], ssum));
      g_cand[b][base + k - 1] = s_neigh[k];
    }
  }
  __syncthreads();

  // gumbel-max over L=1906, partitionable threefry:
  // bits[i] = o0 ^ o1 of threefry2x32(key, (0, i)), i = b*L + l
  uint32_t k0 = g_keys[t][0], k1 = g_keys[t][1];
  float bv = -3.4e38f; int bi = 0x7fffffff;
  for (int l = tid; l < Lk; l += 256) {
    float pr = g_prob[b][l];
    float logit = (pr > 0.0f) ? logf(fmaxf(pr, 1e-38f)) : -1e30f;
    uint32_t i = (uint32_t)(b * Lk + l);
    uint32_t o0, o1;
    tf2x32(k0, k1, 0u, i, o0, o1);
    uint32_t bits = o0 ^ o1;
    float u0 = __fadd_rn(__uint_as_float((bits >> 9) | 0x3f800000u), -1.0f);
    float u = fmaxf(TINYF, __fadd_rn(u0, TINYF));
    float gq = -logf(-logf(u));
    float v = __fadd_rn(logit, gq);
    if (v > bv) { bv = v; bi = l; }   // strict > keeps earliest l per thread
  }
  s_val[tid] = bv; s_idx[tid] = bi;
  __syncthreads();

  if (tid == 0) {
    float bestv = s_val[0]; int besti = s_idx[0];
    for (int i = 1; i < 256; i++) {
      float v = s_val[i];
      if (v > bestv || (v == bestv && s_idx[i] < besti)) { bestv = v; besti = s_idx[i]; }
    }
    int nm = g_cand[b][besti];
    float snp = g_nrec[b][besti];
    float ssp = g_prob[b][besti];
    int col = t + 1;
    out[0 * 16384 + b * Sk + col] = (float)nm;
    out[1 * 16384 + b * Sk + col] = newt;
    out[2 * 16384 + b * Sk + col] = (newt < 1000.0f) ? 1.0f : 0.0f;
    out[3 * 16384 + b * Sk + col] = snp;
    out[4 * 16384 + b * Sk + col] = ssp;
    g_chosen[b] = besti;
    g_last_m[b] = nm;
    g_last_t[b] = newt;
  }
}

extern "C" void kernel_launch(void* const* d_in, const int* in_sizes, int n_in,
                              void* d_out, int out_size) {
  const int*   marker = (const int*)d_in[0];
  const float* timed  = (const float*)d_in[1];
  const float* maskd  = (const float*)d_in[2];
  const float* emb    = (const float*)d_in[3];
  const int*   nlist  = (const int*)d_in[4];
  const float* nprob  = (const float*)d_in[5];
  const float* W_te   = (const float*)d_in[6];
  const float* b_te   = (const float*)d_in[7];
  const float* W_el   = (const float*)d_in[8];
  const float* b_el   = (const float*)d_in[9];
  const float* W_ih   = (const float*)d_in[10];
  const float* b_ih   = (const float*)d_in[11];
  const float* W_hh   = (const float*)d_in[12];
  const float* b_hh   = (const float*)d_in[13];
  const float* W_time = (const float*)d_in[14];
  const float* b_time = (const float*)d_in[15];
  const float* W_mk   = (const float*)d_in[16];
  const float* b_mk   = (const float*)d_in[17];
  float* out = (float*)d_out;

  int total = Bk * Rk;
  init_kernel<<<(total + 255) / 256, 256>>>(marker, timed, maskd, out);
  for (int t = 0; t < Tk; t++) {
    kx_kernel<<<dim3(16, 8), 256>>>(emb, W_te, b_te, W_el, b_el);
    kh_kernel<<<dim3(16, 8), 256>>>(W_ih, b_ih, W_hh, b_hh, t & 1, (t + 1) & 1);
    ks_kernel<<<128, 256>>>(emb, nlist, nprob, W_time, b_time, W_mk, b_mk,
                            (t + 1) & 1, t, out);
  }
}

// round 3
// speedup vs baseline: 1.5639x; 1.5639x over previous
#include <cuda_runtime.h>
#include <cstdint>

#define Bk 128
#define Sk 128
#define Ek 256
#define Dk 512
#define Kk 16
#define Lk 1906
#define Rk 2033
#define Tk 127
#define GRIDB 128u
#define TINYF 1.17549435e-38f

__device__ float g_h[2][Bk][Dk];
__device__ float g_x[Bk][Dk];
__device__ float g_last_t[Bk];
__device__ int   g_last_m[Bk];
__device__ int   g_chosen[Bk];
__device__ int   g_cand[Bk][Lk];
__device__ float g_prob[Bk][Lk];
__device__ float g_nrec[Bk][Rk];
__device__ unsigned g_bar;

// JAX threefry2x32 (exact)
__device__ __forceinline__ void tf2x32(uint32_t k0, uint32_t k1,
                                       uint32_t x0, uint32_t x1,
                                       uint32_t& o0, uint32_t& o1) {
  uint32_t ks2 = k0 ^ k1 ^ 0x1BD11BDAu;
  x0 += k0; x1 += k1;
#define RR(d) { x0 += x1; x1 = (x1 << d) | (x1 >> (32 - d)); x1 ^= x0; }
  RR(13) RR(15) RR(26) RR(6)  x0 += k1;  x1 += ks2 + 1u;
  RR(17) RR(29) RR(16) RR(24) x0 += ks2; x1 += k0 + 2u;
  RR(13) RR(15) RR(26) RR(6)  x0 += k0;  x1 += k1 + 3u;
  RR(17) RR(29) RR(16) RR(24) x0 += k1;  x1 += ks2 + 4u;
  RR(13) RR(15) RR(26) RR(6)  x0 += ks2; x1 += k0 + 5u;
#undef RR
  o0 = x0; o1 = x1;
}

__global__ void reset_kernel() { g_bar = 0u; }

__device__ __forceinline__ void gbar(unsigned& epoch) {
  __syncthreads();
  if (threadIdx.x == 0) {
    __threadfence();
    epoch += GRIDB;
    atomicAdd(&g_bar, 1u);
    while (*((volatile unsigned*)&g_bar) < epoch) { }
    __threadfence();
  }
  __syncthreads();
}

__global__ void __launch_bounds__(256, 1)
rnn_persistent(const int* __restrict__ marker,
               const float* __restrict__ timed,
               const float* __restrict__ maskd,
               const float* __restrict__ emb,
               const int* __restrict__ nlist,
               const float* __restrict__ nprob,
               const float* __restrict__ W_te,
               const float* __restrict__ b_te,
               const float* __restrict__ W_el,
               const float* __restrict__ b_el,
               const float* __restrict__ W_ih,
               const float* __restrict__ b_ih,
               const float* __restrict__ W_hh,
               const float* __restrict__ b_hh,
               const float* __restrict__ W_time,
               const float* __restrict__ b_time,
               const float* __restrict__ W_mk,
               const float* __restrict__ b_mk,
               float* __restrict__ out) {
  __shared__ __align__(16) float SM[9216];
  const int BID = blockIdx.x;
  const int tid = threadIdx.x;
  const int bc = BID & 3;     // batch tile (32 rows)
  const int dc = BID >> 2;    // d tile (16 cols)
  const int myb = BID;        // phase-C row
  unsigned epoch = 0;

  // ---------------- init (each block its own row) ----------------
  for (int l = tid; l < Lk; l += 256) {
    g_prob[myb][l] = (l == 0) ? 1.0f : 0.0f;
    g_cand[myb][l] = (l == 0) ? marker[myb * Sk] : 0;
  }
  for (int r = tid; r < Rk; r += 256) g_nrec[myb][r] = 1.0f;
  for (int d = tid; d < Dk; d += 256) g_h[0][myb][d] = 0.0f;
  if (tid == 0) {
    g_last_t[myb] = timed[myb * Sk];
    g_last_m[myb] = marker[myb * Sk];
    g_chosen[myb] = 0;
    out[0 * 16384 + myb * Sk] = (float)marker[myb * Sk];
    out[1 * 16384 + myb * Sk] = timed[myb * Sk];
    out[2 * 16384 + myb * Sk] = maskd[myb * Sk];
    out[3 * 16384 + myb * Sk] = 1.0f;
    out[4 * 16384 + myb * Sk] = 1.0f;
  }
  gbar(epoch);

  for (int t = 0; t < Tk; t++) {
    // ============ Phase A: x = leaky(vec @ W_el + b_el) ============
    {
      float* sV = SM;  // [32][257]
      int e = tid;     // fixed column per thread (tid < 256)
      float wte = W_te[e], bte = b_te[e];
      for (int bl = 0; bl < 32; bl++) {
        int b = bc * 32 + bl;
        float te = __fadd_rn(__fmul_rn(g_last_t[b], wte), bte);
        sV[bl * 257 + e] = __fadd_rn(emb[(size_t)g_last_m[b] * Ek + e],
                                     __fmul_rn(0.1f, te));
      }
      __syncthreads();
      int dl = tid & 15, bh = tid >> 4;
      int d = dc * 16 + dl;
      const float* wp = W_el + d;
      const float* v0 = sV + bh * 257;
      const float* v1 = sV + (bh + 16) * 257;
      float a0 = 0.0f, a1 = 0.0f;
#pragma unroll 8
      for (int e2 = 0; e2 < Ek; e2++) {
        float w = wp[e2 * Dk];
        a0 = fmaf(v0[e2], w, a0);
        a1 = fmaf(v1[e2], w, a1);
      }
      float bb = b_el[d];
      a0 = __fadd_rn(a0, bb);
      a1 = __fadd_rn(a1, bb);
      g_x[(bc * 32 + bh)][d]      = (a0 >= 0.0f) ? a0 : __fmul_rn(0.01f, a0);
      g_x[(bc * 32 + bh + 16)][d] = (a1 >= 0.0f) ? a1 : __fmul_rn(0.01f, a1);
    }
    gbar(epoch);

    // ============ Phase B: h = tanh(x@W_ih + b_ih + h@W_hh + b_hh) ============
    {
      float* sx = SM;                // [32][136]
      float* sh = SM + 32 * 136;     // [32][136]
      const float* hin = &g_h[t & 1][0][0];
      int dp = tid & 7, bl = tid >> 3;
      int b = bc * 32 + bl;
      int d0 = dc * 16 + dp * 2;
      float ax0 = 0, ax1 = 0, ah0 = 0, ah1 = 0;
      for (int ch = 0; ch < 4; ch++) {
        __syncthreads();
        {
          int e = tid & 127, rb0 = tid >> 7;  // rb0 in {0,1}
          for (int k = 0; k < 16; k++) {
            int rb = rb0 + 2 * k;
            sx[rb * 136 + e] = g_x[bc * 32 + rb][ch * 128 + e];
            sh[rb * 136 + e] = hin[(bc * 32 + rb) * Dk + ch * 128 + e];
          }
        }
        __syncthreads();
        const float* wi = W_ih + (ch * 128) * Dk + d0;
        const float* wh = W_hh + (ch * 128) * Dk + d0;
        const float* px = sx + bl * 136;
        const float* ph = sh + bl * 136;
#pragma unroll 4
        for (int e4 = 0; e4 < 128; e4 += 4) {
          float4 xv = *(const float4*)(px + e4);
          float4 hv = *(const float4*)(ph + e4);
          {
            float2 w1 = *(const float2*)(wi + (e4 + 0) * Dk);
            float2 w2 = *(const float2*)(wh + (e4 + 0) * Dk);
            ax0 = fmaf(xv.x, w1.x, ax0); ax1 = fmaf(xv.x, w1.y, ax1);
            ah0 = fmaf(hv.x, w2.x, ah0); ah1 = fmaf(hv.x, w2.y, ah1);
          }
          {
            float2 w1 = *(const float2*)(wi + (e4 + 1) * Dk);
            float2 w2 = *(const float2*)(wh + (e4 + 1) * Dk);
            ax0 = fmaf(xv.y, w1.x, ax0); ax1 = fmaf(xv.y, w1.y, ax1);
            ah0 = fmaf(hv.y, w2.x, ah0); ah1 = fmaf(hv.y, w2.y, ah1);
          }
          {
            float2 w1 = *(const float2*)(wi + (e4 + 2) * Dk);
            float2 w2 = *(const float2*)(wh + (e4 + 2) * Dk);
            ax0 = fmaf(xv.z, w1.x, ax0); ax1 = fmaf(xv.z, w1.y, ax1);
            ah0 = fmaf(hv.z, w2.x, ah0); ah1 = fmaf(hv.z, w2.y, ah1);
          }
          {
            float2 w1 = *(const float2*)(wi + (e4 + 3) * Dk);
            float2 w2 = *(const float2*)(wh + (e4 + 3) * Dk);
            ax0 = fmaf(xv.w, w1.x, ax0); ax1 = fmaf(xv.w, w1.y, ax1);
            ah0 = fmaf(hv.w, w2.x, ah0); ah1 = fmaf(hv.w, w2.y, ah1);
          }
        }
      }
      float bi0 = b_ih[d0], bi1 = b_ih[d0 + 1];
      float bh0 = b_hh[d0], bh1 = b_hh[d0 + 1];
      float* hout = &g_h[(t + 1) & 1][0][0];
      hout[b * Dk + d0]     = tanhf(__fadd_rn(__fadd_rn(__fadd_rn(ax0, bi0), ah0), bh0));
      hout[b * Dk + d0 + 1] = tanhf(__fadd_rn(__fadd_rn(__fadd_rn(ax1, bi1), ah1), bh1));
    }
    gbar(epoch);

    // ============ Phase C: sampling step for row myb ============
    {
      float* sE = SM;                    // [16][256]
      float* hb = SM + 4096;             // [512]
      float* red = SM + 4608;            // [256]
      int*   ri  = (int*)(SM + 4864);    // [256]
      int*   s_neigh = (int*)(SM + 5120);// [16]
      float* s_score = SM + 5140;        // [16]

      hb[tid] = g_h[(t + 1) & 1][myb][tid];
      hb[tid + 256] = g_h[(t + 1) & 1][myb][tid + 256];
      int lm = g_last_m[myb];
      if (tid < Kk) {
        s_neigh[tid] = nlist[lm * Kk + tid];
        g_nrec[myb][1 + t * Kk + tid] = nprob[lm * Kk + tid];
      }
      __syncthreads();

      // stage emb rows of neighbors
      {
        int e = tid;
        for (int k = 0; k < Kk; k++)
          sE[k * 256 + e] = emb[(size_t)s_neigh[k] * Ek + e];
      }

      // dt partial + tree reduce
      {
        float a = __fmul_rn(hb[2 * tid], W_time[2 * tid]);
        a = fmaf(hb[2 * tid + 1], W_time[2 * tid + 1], a);
        red[tid] = a;
      }
      __syncthreads();
      for (int s = 128; s > 0; s >>= 1) {
        if (tid < s) red[tid] = __fadd_rn(red[tid], red[tid + s]);
        __syncthreads();
      }
      float newt = 0.0f;
      if (tid == 0) {
        float xx = __fadd_rn(red[0], b_time[0]);
        float sp = __fadd_rn(fmaxf(xx, 0.0f), log1pf(expf(-fabsf(xx))));
        newt = __fadd_rn(g_last_t[myb], sp);
      }

      // neighbor scores from smem
      int warp = tid >> 5, lane = tid & 31;
      for (int k = warp; k < Kk; k += 8) {
        const float* ev = sE + k * 256;
        float acc = 0.0f;
        for (int i = lane; i < Ek + Dk; i += 32) {
          float v = (i < Ek) ? ev[i] : hb[i - Ek];
          acc = fmaf(v, W_mk[i], acc);
        }
        for (int o = 16; o; o >>= 1) acc += __shfl_down_sync(0xffffffffu, acc, o);
        if (lane == 0) s_score[k] = __fadd_rn(acc, b_mk[0]);
      }
      __syncthreads();

      if (tid == 0) {
        float mx = s_score[0];
        for (int k = 1; k < Kk; k++) mx = fmaxf(mx, s_score[k]);
        float ee[Kk]; float ssum = 0.0f;
        for (int k = 0; k < Kk; k++) {
          ee[k] = expf(__fadd_rn(s_score[k], -mx));
          ssum = __fadd_rn(ssum, ee[k]);
        }
        int ch = g_chosen[myb];
        float cp = g_prob[myb][ch];
        g_prob[myb][ch] = __fmul_rn(cp, __fdiv_rn(ee[0], ssum));
        int base = 1 + t * (Kk - 1);
        for (int k = 1; k < Kk; k++) {
          g_prob[myb][base + k - 1] = __fmul_rn(cp, __fdiv_rn(ee[k], ssum));
          g_cand[myb][base + k - 1] = s_neigh[k];
        }
      }
      __syncthreads();

      // gumbel-max over active prefix (all l >= active have prob==0 exactly
      // -> value exactly -1e30, strictly below any positive-prob entry)
      uint32_t k0, k1;
      tf2x32(0u, 42u, 0u, (uint32_t)t, k0, k1);
      int active = 15 * t + 16;
      if (active > Lk) active = Lk;
      float bv = -3.4e38f; int bi = 0x7fffffff;
      for (int l = tid; l < active; l += 256) {
        float pr = g_prob[myb][l];
        float logit = (pr > 0.0f) ? logf(fmaxf(pr, 1e-38f)) : -1e30f;
        uint32_t i = (uint32_t)(myb * Lk + l);
        uint32_t o0, o1;
        tf2x32(k0, k1, 0u, i, o0, o1);
        uint32_t bits = o0 ^ o1;
        float u0 = __fadd_rn(__uint_as_float((bits >> 9) | 0x3f800000u), -1.0f);
        float u = fmaxf(TINYF, __fadd_rn(u0, TINYF));
        float gq = -logf(-logf(u));
        float v = __fadd_rn(logit, gq);
        if (v > bv) { bv = v; bi = l; }
      }
      red[tid] = bv; ri[tid] = bi;
      __syncthreads();
      for (int s = 128; s > 0; s >>= 1) {
        if (tid < s) {
          float v2 = red[tid + s]; int i2 = ri[tid + s];
          if (v2 > red[tid] || (v2 == red[tid] && i2 < ri[tid])) {
            red[tid] = v2; ri[tid] = i2;
          }
        }
        __syncthreads();
      }

      if (tid == 0) {
        int besti = ri[0];
        int nm = g_cand[myb][besti];
        float snp = g_nrec[myb][besti];
        float ssp = g_prob[myb][besti];
        int col = t + 1;
        out[0 * 16384 + myb * Sk + col] = (float)nm;
        out[1 * 16384 + myb * Sk + col] = newt;
        out[2 * 16384 + myb * Sk + col] = (newt < 1000.0f) ? 1.0f : 0.0f;
        out[3 * 16384 + myb * Sk + col] = snp;
        out[4 * 16384 + myb * Sk + col] = ssp;
        g_chosen[myb] = besti;
        g_last_m[myb] = nm;
        g_last_t[myb] = newt;
      }
    }
    gbar(epoch);
  }
}

extern "C" void kernel_launch(void* const* d_in, const int* in_sizes, int n_in,
                              void* d_out, int out_size) {
  const int*   marker = (const int*)d_in[0];
  const float* timed  = (const float*)d_in[1];
  const float* maskd  = (const float*)d_in[2];
  const float* emb    = (const float*)d_in[3];
  const int*   nlist  = (const int*)d_in[4];
  const float* nprob  = (const float*)d_in[5];
  const float* W_te   = (const float*)d_in[6];
  const float* b_te   = (const float*)d_in[7];
  const float* W_el   = (const float*)d_in[8];
  const float* b_el   = (const float*)d_in[9];
  const float* W_ih   = (const float*)d_in[10];
  const float* b_ih   = (const float*)d_in[11];
  const float* W_hh   = (const float*)d_in[12];
  const float* b_hh   = (const float*)d_in[13];
  const float* W_time = (const float*)d_in[14];
  const float* b_time = (const float*)d_in[15];
  const float* W_mk   = (const float*)d_in[16];
  const float* b_mk   = (const float*)d_in[17];
  float* out = (float*)d_out;

  reset_kernel<<<1, 1>>>();
  rnn_persistent<<<GRIDB, 256>>>(marker, timed, maskd, emb, nlist, nprob,
                                 W_te, b_te, W_el, b_el, W_ih, b_ih,
                                 W_hh, b_hh, W_time, b_time, W_mk, b_mk, out);
}